// round 8
// baseline (speedup 1.0000x reference)
#include <cuda_runtime.h>

// RSLDS forward-backward smoother, B=8 T=1024 N=64 K=8.
// Outputs: forward | backward | gamma1 | gamma2 (concatenated in d_out).
//
// Blocked scan:
//   pass1: per-(chain,segment) 8x8 transfer-matrix products (linear)
//   pass2: sequential scan over segments -> boundary vectors (g_Vb, g_Rb)
//   pass3_fw: per-segment forward recursion -> unnormalized log2 alphas (g_fwu)
//   bwgamma: per-segment backward recursion FUSED with all posterior emission
//            (writes fw, bw, gamma1, gamma2 outputs directly; no bwu scratch,
//             no separate gamma kernel, la read once here instead of twice).

#define FULLMASK 0xffffffffu
constexpr int B_ = 8, T_ = 1024, N_ = 64, K_ = 8;
constexpr int C_ = B_ * N_;          // 512 chains
constexpr int L_ = 32, S_ = 32;      // segment length, count
constexpr int TN = T_ * N_;
constexpr long long BTNK = (long long)B_ * T_ * N_ * K_;

__device__ float g_Q  [C_ * S_ * 64];  // segment transfer matrices (linear)
__device__ float g_Vb [C_ * S_ * 8];   // fw boundaries (linear, rescaled)
__device__ float g_Rb [C_ * S_ * 8];   // bw boundaries (linear, rescaled)
__device__ float g_fwu[BTNK];          // unnormalized log2 alpha'

__device__ __forceinline__ float ex2f(float x) {
    float y; asm("ex2.approx.ftz.f32 %0, %1;" : "=f"(y) : "f"(x)); return y;
}
__device__ __forceinline__ float lg2f(float x) {
    float y; asm("lg2.approx.f32 %0, %1;" : "=f"(y) : "f"(x)); return y;
}
__device__ __forceinline__ float rcpf(float x) {
    float y; asm("rcp.approx.ftz.f32 %0, %1;" : "=f"(y) : "f"(x)); return y;
}

#define L2E 1.4426950408889634f
#define LN2 0.6931471805599453f

// ---------------------------------------------------------------------------
// pass1: Q_s = M_te ... M_ts,  M_t[i,j] = exp(log_b_t[i] + log_a_t[i,j]).
// lane (i = lane>>2, q = lane&3) holds Q[i,2q], Q[i,2q+1]. Rescale every 4 steps.
// ---------------------------------------------------------------------------
__global__ void __launch_bounds__(128) pass1_kernel(
    const float* __restrict__ la, const float* __restrict__ lb)
{
    const int w    = blockIdx.x * 4 + (threadIdx.x >> 5);
    const int lane = threadIdx.x & 31;
    const int q    = lane & 3;
    const int i    = lane >> 2;
    const int c = w >> 5, s = w & 31;
    const int b = c >> 6, n = c & 63;
    const int tile0 = b * TN + n;

    const int ts = (s == 0) ? 1 : s * L_;
    const int te = s * L_ + L_ - 1;

    const float2* ap = (const float2*)la + (tile0 + ts * N_) * 32 + lane;
    const float*  bp = lb + (tile0 + ts * N_) * 8 + i;

    float Qx, Qy;
    {   // Q = M_ts
        float2 a2 = *ap;
        float  bi = *bp;
        Qx = ex2f((a2.x + bi) * L2E);
        Qy = ex2f((a2.y + bi) * L2E);
        ap += 32 * N_; bp += 8 * N_;
    }

    int cnt = 0;
    for (int t = ts + 1; t <= te; t++) {
        float2 a2 = *ap;
        float  bi = *bp;
        ap += 32 * N_; bp += 8 * N_;
        float mtx = ex2f((a2.x + bi) * L2E);   // mt[i,2q]
        float mty = ex2f((a2.y + bi) * L2E);   // mt[i,2q+1]

        float nx = 0.f, ny = 0.f;
        #pragma unroll
        for (int j2 = 0; j2 < 4; j2++) {
            float ma = __shfl_sync(FULLMASK, mtx, j2, 4);          // mt[i,2j2]
            float mb = __shfl_sync(FULLMASK, mty, j2, 4);          // mt[i,2j2+1]
            float qxa = __shfl_sync(FULLMASK, Qx, 8 * j2 + q);     // Q[2j2,2q]
            float qya = __shfl_sync(FULLMASK, Qy, 8 * j2 + q);     // Q[2j2,2q+1]
            float qxb = __shfl_sync(FULLMASK, Qx, 8 * j2 + 4 + q); // Q[2j2+1,2q]
            float qyb = __shfl_sync(FULLMASK, Qy, 8 * j2 + 4 + q); // Q[2j2+1,2q+1]
            nx = fmaf(ma, qxa, fmaf(mb, qxb, nx));
            ny = fmaf(ma, qya, fmaf(mb, qyb, ny));
        }
        Qx = nx; Qy = ny;
        if ((++cnt & 3) == 0 || t == te) {     // rescale every 4 steps + final
            float m = fmaxf(Qx, Qy);
            m = fmaxf(m, __shfl_xor_sync(FULLMASK, m, 1));
            m = fmaxf(m, __shfl_xor_sync(FULLMASK, m, 2));
            m = fmaxf(m, __shfl_xor_sync(FULLMASK, m, 4));
            m = fmaxf(m, __shfl_xor_sync(FULLMASK, m, 8));
            m = fmaxf(m, __shfl_xor_sync(FULLMASK, m, 16));
            float inv = rcpf(m);
            Qx *= inv; Qy *= inv;
        }
    }
    *(float2*)(g_Q + (size_t)(c * S_ + s) * 64 + lane * 2) = make_float2(Qx, Qy);
}

// ---------------------------------------------------------------------------
// pass2: sequential scan over segments. warp = (dir, chain).
// ---------------------------------------------------------------------------
__global__ void __launch_bounds__(128) pass2_kernel(
    const float* __restrict__ lb, const float* __restrict__ lz)
{
    const int w    = blockIdx.x * 4 + (threadIdx.x >> 5);
    const int lane = threadIdx.x & 31;
    const int q    = lane & 3;
    const int i    = lane >> 2;
    const bool is_bw = (w >= C_);
    const int c = is_bw ? w - C_ : w;
    const int b = c >> 6, n = c & 63;
    const int tile0 = b * TN + n;

    if (!is_bw) {
        float x = lz[n * 8 + i] + lb[tile0 * 8 + i];
        float m0 = x;
        m0 = fmaxf(m0, __shfl_xor_sync(FULLMASK, m0, 4));
        m0 = fmaxf(m0, __shfl_xor_sync(FULLMASK, m0, 8));
        m0 = fmaxf(m0, __shfl_xor_sync(FULLMASK, m0, 16));
        float vi = ex2f((x - m0) * L2E);       // v[i], replicated over q

        for (int s = 0; s <= 30; s++) {
            float2 Qr = *(const float2*)(g_Q + (size_t)(c * S_ + s) * 64 + lane * 2);
            float vx = __shfl_sync(FULLMASK, vi, 8 * q);
            float vy = __shfl_sync(FULLMASK, vi, 8 * q + 4);
            float p = fmaf(Qr.x, vx, Qr.y * vy);
            p += __shfl_xor_sync(FULLMASK, p, 1);
            p += __shfl_xor_sync(FULLMASK, p, 2);
            float m = p;
            m = fmaxf(m, __shfl_xor_sync(FULLMASK, m, 4));
            m = fmaxf(m, __shfl_xor_sync(FULLMASK, m, 8));
            m = fmaxf(m, __shfl_xor_sync(FULLMASK, m, 16));
            vi = p * rcpf(m);
            if (q == 0) g_Vb[(size_t)(c * S_ + s + 1) * 8 + i] = vi;
        }
    } else {
        float ri = 1.0f;
        for (int s = 31; s >= 1; s--) {
            float2 Qr = *(const float2*)(g_Q + (size_t)(c * S_ + s) * 64 + lane * 2);
            float pe = Qr.x * ri;
            float po = Qr.y * ri;
            pe += __shfl_xor_sync(FULLMASK, pe, 4);
            pe += __shfl_xor_sync(FULLMASK, pe, 8);
            pe += __shfl_xor_sync(FULLMASK, pe, 16);
            po += __shfl_xor_sync(FULLMASK, po, 4);
            po += __shfl_xor_sync(FULLMASK, po, 8);
            po += __shfl_xor_sync(FULLMASK, po, 16);
            float re = __shfl_sync(FULLMASK, pe, i >> 1);
            float ro = __shfl_sync(FULLMASK, po, i >> 1);
            float rn = (i & 1) ? ro : re;
            float m = fmaxf(pe, po);
            m = fmaxf(m, __shfl_xor_sync(FULLMASK, m, 1));
            m = fmaxf(m, __shfl_xor_sync(FULLMASK, m, 2));
            ri = rn * rcpf(m);
            if (q == 0) g_Rb[(size_t)(c * S_ + s) * 8 + i] = ri;
        }
    }
}

// ---------------------------------------------------------------------------
// pass3_fw: forward recursion per (chain,segment), emits unnormalized log2
// alphas into g_fwu. lane (i=rr, ii) handles j-pair 2ii,2ii+1 of row i.
// ---------------------------------------------------------------------------
__global__ void __launch_bounds__(128) pass3_fw_kernel(
    const float* __restrict__ la, const float* __restrict__ lb,
    const float* __restrict__ lz)
{
    const int w    = blockIdx.x * 4 + (threadIdx.x >> 5);
    const int lane = threadIdx.x & 31;
    const int ii   = lane & 3;
    const int rr   = lane >> 2;
    const int c = w >> 5, s = w & 31;
    const int b = c >> 6, n = c & 63;
    const int tile0 = b * TN + n;
    const int sel0 = ii * 8, sel1 = ii * 8 + 4;

    float prev;
    int t0;
    if (s == 0) {
        prev = (lz[n * 8 + rr] + lb[tile0 * 8 + rr]) * L2E;
        if (ii == 0) g_fwu[tile0 * 8 + rr] = prev;
        t0 = 1;
    } else {
        prev = lg2f(g_Vb[(c * S_ + s) * 8 + rr]);
        t0 = s * L_;
    }
    const int t1 = s * L_ + L_ - 1;

    const float2* ap = (const float2*)la + (tile0 + t0 * N_) * 32 + lane;
    const float*  bp = lb + (tile0 + t0 * N_) * 8 + rr;
    float*        op = g_fwu + (tile0 + t0 * N_) * 8 + rr;

    for (int t = t0; t <= t1; t++) {
        float2 av = *ap;
        float  bv = *bp;
        ap += 32 * N_; bp += 8 * N_;
        float p0 = __shfl_sync(FULLMASK, prev, sel0);
        float p1 = __shfl_sync(FULLMASK, prev, sel1);
        float u0 = __shfl_sync(FULLMASK, prev, 0);
        float e = ex2f(fmaf(av.x, L2E, p0 - u0))
                + ex2f(fmaf(av.y, L2E, p1 - u0));
        e += __shfl_xor_sync(FULLMASK, e, 1);
        e += __shfl_xor_sync(FULLMASK, e, 2);
        float uu = fmaf(bv, L2E, lg2f(e));
        prev = uu;
        if (ii == 0) *op = uu;
        op += 8 * N_;
    }
}

// ---------------------------------------------------------------------------
// bwgamma: backward recursion fused with ALL posterior output emission.
// Warp = (chain, segment). lane (j=rr, ii) handles i-pair 2ii,2ii+1 of col j.
// Step computing beta_t emits outputs for time t+1; extra step emits time s*L.
// ---------------------------------------------------------------------------
__global__ void __launch_bounds__(128) bwgamma_kernel(
    const float* __restrict__ la, const float* __restrict__ lb,
    float* __restrict__ fw, float* __restrict__ bwo,
    float* __restrict__ g1, float* __restrict__ g2)
{
    const int w    = blockIdx.x * 4 + (threadIdx.x >> 5);
    const int lane = threadIdx.x & 31;
    const int ii   = lane & 3;
    const int rr   = lane >> 2;
    const int c = w >> 5, s = w & 31;
    const int b = c >> 6, n = c & 63;
    const int tile0 = b * TN + n;
    const int sel0 = ii * 8, sel1 = ii * 8 + 4;
    const int te = s * L_ + L_ - 1;

    // beta_{te} (anchored log2) and fwu[te]
    float prev  = (s == 31) ? 0.0f : lg2f(g_Rb[(c * S_ + s + 1) * 8 + rr]);
    float fprev = g_fwu[(tile0 + te * N_) * 8 + rr];

    const float*  cp  = la + (tile0 + te * N_) * 64 + ii * 16 + rr;
    const float2* bp2 = (const float2*)lb + (tile0 + te * N_) * 4 + ii;
    const float*  fp  = g_fwu + (tile0 + (te - 1) * N_) * 8 + rr;
    int ob  = (tile0 + te * N_) * 8 + rr;       // fw/bw/g1 (pred ii==0)
    int g2b = (tile0 + te * N_) * 64;           // gamma2 tile base

    const bool top = (s == 31);

    for (int t = te - 1; t >= s * L_; t--) {
        float  c0 = cp[0];            // la_{t+1}[2ii][j]
        float  c1 = cp[8];            // la_{t+1}[2ii+1][j]
        float2 bv = *bp2;             // lb_{t+1}[2ii], [2ii+1]
        float fcur = *fp;             // fwu[t]
        cp -= 64 * N_; bp2 -= 4 * N_; fp -= 8 * N_;

        // recursion core (beta_{t+1} -> beta_t)
        float p0 = __shfl_sync(FULLMASK, prev, sel0);
        float p1 = __shfl_sync(FULLMASK, prev, sel1);
        float u0 = __shfl_sync(FULLMASK, prev, 0);
        float a0 = fmaf(c0 + bv.x, L2E, p0 - u0);
        float a1 = fmaf(c1 + bv.y, L2E, p1 - u0);
        float e  = ex2f(a0) + ex2f(a1);
        e += __shfl_xor_sync(FULLMASK, e, 1);
        e += __shfl_xor_sync(FULLMASK, e, 2);   // e(rr) = sum over i

        // ---- emissions for time t+1 ----
        // bw output: normalize(beta_{t+1}) over rr  (raw zeros at t+1 == 1023)
        float eb = ex2f(prev);
        eb += __shfl_xor_sync(FULLMASK, eb, 4);
        eb += __shfl_xor_sync(FULLMASK, eb, 8);
        eb += __shfl_xor_sync(FULLMASK, eb, 16);
        float bwout = (top && t == te - 1) ? 0.0f : (prev - lg2f(eb)) * LN2;
        // fw output: normalize(fwu[t+1]) over rr
        float ef = ex2f(fprev);
        ef += __shfl_xor_sync(FULLMASK, ef, 4);
        ef += __shfl_xor_sync(FULLMASK, ef, 8);
        ef += __shfl_xor_sync(FULLMASK, ef, 16);
        float fwout = (fprev - lg2f(ef)) * LN2;
        // gamma1: normalize(fwu[t+1] + beta_{t+1})
        float v  = fprev + prev;
        float eg = ex2f(v);
        eg += __shfl_xor_sync(FULLMASK, eg, 4);
        eg += __shfl_xor_sync(FULLMASK, eg, 8);
        eg += __shfl_xor_sync(FULLMASK, eg, 16);
        float g1out = (v - lg2f(eg)) * LN2;
        if (ii == 0) { fw[ob] = fwout; bwo[ob] = bwout; g1[ob] = g1out; }
        // gamma2[t+1][i][j] = a_i + fwu_t[j] - lse (shifts cancel)
        float fj = ex2f(fcur);
        float z  = e * fj;                       // per-rr column sum
        z += __shfl_xor_sync(FULLMASK, z, 4);
        z += __shfl_xor_sync(FULLMASK, z, 8);
        z += __shfl_xor_sync(FULLMASK, z, 16);
        float tt = fcur - lg2f(z);
        g2[g2b + 16 * ii + rr]     = (a0 + tt) * LN2;
        g2[g2b + 16 * ii + 8 + rr] = (a1 + tt) * LN2;

        // finish recursion
        prev  = lg2f(e);
        fprev = fcur;
        ob -= 8 * N_; g2b -= 64 * N_;
    }

    // ---- extra emission for time t = s*L (prev = beta_{sL}, fprev = fwu[sL]) ----
    {
        float eb = ex2f(prev);
        eb += __shfl_xor_sync(FULLMASK, eb, 4);
        eb += __shfl_xor_sync(FULLMASK, eb, 8);
        eb += __shfl_xor_sync(FULLMASK, eb, 16);
        float bwout = (prev - lg2f(eb)) * LN2;
        float ef = ex2f(fprev);
        ef += __shfl_xor_sync(FULLMASK, ef, 4);
        ef += __shfl_xor_sync(FULLMASK, ef, 8);
        ef += __shfl_xor_sync(FULLMASK, ef, 16);
        float fwout = (fprev - lg2f(ef)) * LN2;
        float v  = fprev + prev;
        float eg = ex2f(v);
        eg += __shfl_xor_sync(FULLMASK, eg, 4);
        eg += __shfl_xor_sync(FULLMASK, eg, 8);
        eg += __shfl_xor_sync(FULLMASK, eg, 16);
        float g1out = (v - lg2f(eg)) * LN2;
        if (ii == 0) { fw[ob] = fwout; bwo[ob] = bwout; g1[ob] = g1out; }

        if (s == 0) {                            // gamma2[0] = zeros
            g2[g2b + 16 * ii + rr]     = 0.0f;
            g2[g2b + 16 * ii + 8 + rr] = 0.0f;
        } else {                                 // gamma2 at sL, fw from g_Vb
            const float* cpe = la + (tile0 + s * L_ * N_) * 64 + ii * 16 + rr;
            float  c0 = cpe[0];
            float  c1 = cpe[8];
            float2 bv = *((const float2*)lb + (tile0 + s * L_ * N_) * 4 + ii);
            float fm1 = lg2f(g_Vb[(c * S_ + s) * 8 + rr]);   // fwu[sL-1] (shifted)
            float p0 = __shfl_sync(FULLMASK, prev, sel0);
            float p1 = __shfl_sync(FULLMASK, prev, sel1);
            float u0 = __shfl_sync(FULLMASK, prev, 0);
            float a0 = fmaf(c0 + bv.x, L2E, p0 - u0);
            float a1 = fmaf(c1 + bv.y, L2E, p1 - u0);
            float e  = ex2f(a0) + ex2f(a1);
            e += __shfl_xor_sync(FULLMASK, e, 1);
            e += __shfl_xor_sync(FULLMASK, e, 2);
            float fj = ex2f(fm1);
            float z  = e * fj;
            z += __shfl_xor_sync(FULLMASK, z, 4);
            z += __shfl_xor_sync(FULLMASK, z, 8);
            z += __shfl_xor_sync(FULLMASK, z, 16);
            float tt = fm1 - lg2f(z);
            g2[g2b + 16 * ii + rr]     = (a0 + tt) * LN2;
            g2[g2b + 16 * ii + 8 + rr] = (a1 + tt) * LN2;
        }
    }
}

extern "C" void kernel_launch(void* const* d_in, const int* in_sizes, int n_in,
                              void* d_out, int out_size) {
    const float* la = (const float*)d_in[0];   // log_a  (B,T,N,K,K)
    const float* lb = (const float*)d_in[1];   // log_b  (B,T,N,K)
    const float* lz = (const float*)d_in[2];   // logprob_z1 (N,K)

    float* out = (float*)d_out;
    float* fw = out;
    float* bw = fw + BTNK;
    float* g1 = bw + BTNK;
    float* g2 = g1 + BTNK;

    pass1_kernel<<<(C_ * S_) / 4, 128>>>(la, lb);          // 16384 warps
    pass2_kernel<<<(2 * C_) / 4, 128>>>(lb, lz);           // 1024 warps
    pass3_fw_kernel<<<(C_ * S_) / 4, 128>>>(la, lb, lz);   // 16384 warps
    bwgamma_kernel<<<(C_ * S_) / 4, 128>>>(la, lb, fw, bw, g1, g2);
}